// round 8
// baseline (speedup 1.0000x reference)
#include <cuda_runtime.h>

// out[b,q,d] = sum_k values[b,k,d]  (softmax over singleton axis == 1;
// queries/keys/w_score are dead code). B=4, Q=512, K=512, F=128.
//
// Established across R2-R7: wall is floor-bound (~6.6us graph-replay floor);
// best shape is the feature-split 128-block x 512-thread kernel (R6).
// This round trims the post-barrier tail: addresses precomputed, depth-3
// trees everywhere, 1 STG.128 per thread via streaming hint.

#define B_   4
#define Q_   512
#define K_   512
#define F4   32      // float4 per full feature row
#define FSL4 8       // float4 per feature slice (32 floats = 128 B)
#define QROWS 64     // Q rows written per block

__global__ void __launch_bounds__(512, 1)
feat_split_sum_broadcast(const float4* __restrict__ values,
                         float4* __restrict__ out) {
    __shared__ float4 part[16][FSL4];          // per-warp column partials (2 KB)

    const int b   = blockIdx.x >> 5;           // batch         (0..3)
    const int rem = blockIdx.x & 31;
    const int fsl = rem >> 3;                  // feature slice (0..3)
    const int qsl = rem & 7;                   // Q slice       (0..7)

    const int tid  = threadIdx.x;
    const int w    = tid >> 5;                 // warp 0..15: K rows [w*32, +32)
    const int lane = tid & 31;
    const int c    = lane & 7;                 // float4 column within slice
    const int rsub = lane >> 3;                // row offset 0..3 in 4-row group

    // Precompute the output address BEFORE the load/barrier chain so the
    // post-barrier tail is just LDS-fold + STG.
    const int row = qsl * QROWS + (tid >> 3);
    float4* const ob = out + ((size_t)(b * Q_ + row)) * F4 + fsl * FSL4 + c;

    // ---- Phase 1: each lane streams 8 rows (stride 4) of its 16B column.
    const float4* p = values
        + ((size_t)(b * K_ + w * 32 + rsub)) * F4 + fsl * FSL4 + c;

    float4 v0 = __ldcg(p + 0 * 4 * F4);
    float4 v1 = __ldcg(p + 1 * 4 * F4);
    float4 v2 = __ldcg(p + 2 * 4 * F4);
    float4 v3 = __ldcg(p + 3 * 4 * F4);
    float4 v4 = __ldcg(p + 4 * 4 * F4);
    float4 v5 = __ldcg(p + 5 * 4 * F4);
    float4 v6 = __ldcg(p + 6 * 4 * F4);
    float4 v7 = __ldcg(p + 7 * 4 * F4);

    float4 acc;   // depth-3 pairwise tree
    acc.x = ((v0.x + v1.x) + (v2.x + v3.x)) + ((v4.x + v5.x) + (v6.x + v7.x));
    acc.y = ((v0.y + v1.y) + (v2.y + v3.y)) + ((v4.y + v5.y) + (v6.y + v7.y));
    acc.z = ((v0.z + v1.z) + (v2.z + v3.z)) + ((v4.z + v5.z) + (v6.z + v7.z));
    acc.w = ((v0.w + v1.w) + (v2.w + v3.w)) + ((v4.w + v5.w) + (v6.w + v7.w));

    // ---- Phase 2: fold the 4 row-groups sharing a column (xor 8, 16).
#pragma unroll
    for (int m = 8; m <= 16; m <<= 1) {
        acc.x += __shfl_xor_sync(0xffffffffu, acc.x, m);
        acc.y += __shfl_xor_sync(0xffffffffu, acc.y, m);
        acc.z += __shfl_xor_sync(0xffffffffu, acc.z, m);
        acc.w += __shfl_xor_sync(0xffffffffu, acc.w, m);
    }
    if (lane < FSL4) part[w][lane] = acc;
    __syncthreads();

    // ---- Phase 3: fold 16 warp-partials (broadcast LDS, conflict-free),
    // 4 independent accumulators, depth-limited tree; then one STG.128.
    float4 s0 = part[0][c], s1 = part[1][c], s2 = part[2][c], s3 = part[3][c];
#pragma unroll
    for (int i = 4; i < 16; i += 4) {
        float4 w0 = part[i + 0][c];
        float4 w1 = part[i + 1][c];
        float4 w2 = part[i + 2][c];
        float4 w3 = part[i + 3][c];
        s0.x += w0.x; s0.y += w0.y; s0.z += w0.z; s0.w += w0.w;
        s1.x += w1.x; s1.y += w1.y; s1.z += w1.z; s1.w += w1.w;
        s2.x += w2.x; s2.y += w2.y; s2.z += w2.z; s2.w += w2.w;
        s3.x += w3.x; s3.y += w3.y; s3.z += w3.z; s3.w += w3.w;
    }
    float4 t;
    t.x = (s0.x + s1.x) + (s2.x + s3.x);
    t.y = (s0.y + s1.y) + (s2.y + s3.y);
    t.z = (s0.z + s1.z) + (s2.z + s3.z);
    t.w = (s0.w + s1.w) + (s2.w + s3.w);

    __stcg(ob, t);
}

extern "C" void kernel_launch(void* const* d_in, const int* in_sizes, int n_in,
                              void* d_out, int out_size) {
    // inputs (metadata order): queries, keys, values, w_score
    const float4* values = (const float4*)d_in[2];
    float4* out = (float4*)d_out;
    feat_split_sum_broadcast<<<128, 512>>>(values, out);
}

// round 9
// speedup vs baseline: 1.0721x; 1.0721x over previous
#include <cuda_runtime.h>

// out[b,q,d] = sum_k values[b,k,d]  (softmax over singleton axis == 1;
// queries/keys/w_score are dead code). B=4, Q=512, K=512, F=128.
//
// R2-R8 established: wall is floor-bound (~6.6us) and noise-dominated;
// fastest measured kernel was the 128-block x 256-thread feature-split
// (R5, 5.06us — 8 warps/SM avoids cross-warp L1tex queue contention).
// This version = R5 shape + minimal post-barrier tail:
//   * store addresses hoisted above the load chain
//   * only 8 smem partials to fold after the single barrier
//   * plain STG.128 x2 per thread (streaming hint on loads only)

#define B_   4
#define Q_   512
#define K_   512
#define F4   32      // float4 per full feature row
#define FSL4 8       // float4 per feature slice (32 floats = 128 B)
#define QROWS 64     // Q rows written per block

__global__ void __launch_bounds__(256, 1)
feat_split_sum_broadcast(const float4* __restrict__ values,
                         float4* __restrict__ out) {
    __shared__ float4 part[8][FSL4];           // per-warp column partials (1 KB)

    const int b   = blockIdx.x >> 5;           // batch         (0..3)
    const int rem = blockIdx.x & 31;
    const int fsl = rem >> 3;                  // feature slice (0..3)
    const int qsl = rem & 7;                   // Q slice       (0..7)

    const int tid  = threadIdx.x;
    const int w    = tid >> 5;                 // warp 0..7: K rows [w*64, +64)
    const int lane = tid & 31;
    const int c    = lane & 7;                 // float4 column within slice
    const int rsub = lane >> 3;                // row offset 0..3 in 4-row group

    // Hoist the two output addresses above the load/barrier chain.
    // Thread writes rows (tid/8) and (tid/8 + 32) of its 64-row Q slice.
    const int row0 = qsl * QROWS + (tid >> 3);
    float4* const ob = out + ((size_t)(b * Q_ + row0)) * F4 + fsl * FSL4 + c;

    // ---- Phase 1: each lane streams 16 rows (stride 4) of its 16B column.
    const float4* p = values
        + ((size_t)(b * K_ + w * 64 + rsub)) * F4 + fsl * FSL4 + c;

    float4 a0 = make_float4(0.f,0.f,0.f,0.f);
    float4 a1 = a0, a2 = a0, a3 = a0;
#pragma unroll
    for (int i = 0; i < 16; i += 4) {
        float4 v0 = __ldcg(p + (i + 0) * 4 * F4);
        float4 v1 = __ldcg(p + (i + 1) * 4 * F4);
        float4 v2 = __ldcg(p + (i + 2) * 4 * F4);
        float4 v3 = __ldcg(p + (i + 3) * 4 * F4);
        a0.x += v0.x; a0.y += v0.y; a0.z += v0.z; a0.w += v0.w;
        a1.x += v1.x; a1.y += v1.y; a1.z += v1.z; a1.w += v1.w;
        a2.x += v2.x; a2.y += v2.y; a2.z += v2.z; a2.w += v2.w;
        a3.x += v3.x; a3.y += v3.y; a3.z += v3.z; a3.w += v3.w;
    }
    float4 acc;
    acc.x = (a0.x + a1.x) + (a2.x + a3.x);
    acc.y = (a0.y + a1.y) + (a2.y + a3.y);
    acc.z = (a0.z + a1.z) + (a2.z + a3.z);
    acc.w = (a0.w + a1.w) + (a2.w + a3.w);

    // ---- Phase 2: fold the 4 row-groups sharing a column (xor 8, 16).
#pragma unroll
    for (int m = 8; m <= 16; m <<= 1) {
        acc.x += __shfl_xor_sync(0xffffffffu, acc.x, m);
        acc.y += __shfl_xor_sync(0xffffffffu, acc.y, m);
        acc.z += __shfl_xor_sync(0xffffffffu, acc.z, m);
        acc.w += __shfl_xor_sync(0xffffffffu, acc.w, m);
    }
    if (lane < FSL4) part[w][lane] = acc;
    __syncthreads();

    // ---- Phase 3: fold only 8 warp-partials (broadcast LDS, conflict-free).
    float4 s0 = part[0][c], s1 = part[1][c], s2 = part[2][c], s3 = part[3][c];
    {
        float4 w0 = part[4][c], w1 = part[5][c], w2 = part[6][c], w3 = part[7][c];
        s0.x += w0.x; s0.y += w0.y; s0.z += w0.z; s0.w += w0.w;
        s1.x += w1.x; s1.y += w1.y; s1.z += w1.z; s1.w += w1.w;
        s2.x += w2.x; s2.y += w2.y; s2.z += w2.z; s2.w += w2.w;
        s3.x += w3.x; s3.y += w3.y; s3.z += w3.z; s3.w += w3.w;
    }
    float4 t;
    t.x = (s0.x + s1.x) + (s2.x + s3.x);
    t.y = (s0.y + s1.y) + (s2.y + s3.y);
    t.z = (s0.z + s1.z) + (s2.z + s3.z);
    t.w = (s0.w + s1.w) + (s2.w + s3.w);

    // ---- Phase 4: two coalesced STG.128 per thread (rows r0 and r0+32).
    ob[0]       = t;
    ob[32 * F4] = t;
}

extern "C" void kernel_launch(void* const* d_in, const int* in_sizes, int n_in,
                              void* d_out, int out_size) {
    // inputs (metadata order): queries, keys, values, w_score
    const float4* values = (const float4*)d_in[2];
    float4* out = (float4*)d_out;
    feat_split_sum_broadcast<<<128, 256>>>(values, out);
}

// round 10
// speedup vs baseline: 1.0773x; 1.0048x over previous
#include <cuda_runtime.h>

// out[b,q,d] = sum_k values[b,k,d]  (softmax over singleton axis == 1;
// queries/keys/w_score are dead code). B=4, Q=512, K=512, F=128.
//
// FINAL (converged R9). Session evidence:
//  * wall is pinned at a ~6.6us graph-replay floor, insensitive to kernel
//    dur in the 4.8-6.2us range (R2 vs R9: 6.24 vs 4.77 kernel, same wall)
//  * feature-split 128 blocks x 256 threads is the measured optimum:
//    512 load-wavefronts/block (the floor for a full-K column sum),
//    8 warps/SM avoids cross-warp L1tex queue contention (R7 regression),
//    cross-block sync / 2-kernel variants measured strictly worse (R1/R4).
// Block = (batch, 32-float feature slice, 64-row Q slice). Single barrier.

#define B_   4
#define Q_   512
#define K_   512
#define F4   32      // float4 per full feature row
#define FSL4 8       // float4 per feature slice (32 floats = 128 B)
#define QROWS 64     // Q rows written per block

__global__ void __launch_bounds__(256, 1)
feat_split_sum_broadcast(const float4* __restrict__ values,
                         float4* __restrict__ out) {
    __shared__ float4 part[8][FSL4];           // per-warp column partials (1 KB)

    const int b   = blockIdx.x >> 5;           // batch         (0..3)
    const int rem = blockIdx.x & 31;
    const int fsl = rem >> 3;                  // feature slice (0..3)
    const int qsl = rem & 7;                   // Q slice       (0..7)

    const int tid  = threadIdx.x;
    const int w    = tid >> 5;                 // warp 0..7: K rows [w*64, +64)
    const int lane = tid & 31;
    const int c    = lane & 7;                 // float4 column within slice
    const int rsub = lane >> 3;                // row offset 0..3 in 4-row group

    // Hoist the output address above the load/barrier chain.
    // Thread writes rows (tid/8) and (tid/8 + 32) of its 64-row Q slice.
    const int row0 = qsl * QROWS + (tid >> 3);
    float4* const ob = out + ((size_t)(b * Q_ + row0)) * F4 + fsl * FSL4 + c;

    // ---- Phase 1: each lane streams 16 rows (stride 4) of its 16B column.
    const float4* p = values
        + ((size_t)(b * K_ + w * 64 + rsub)) * F4 + fsl * FSL4 + c;

    float4 a0 = make_float4(0.f,0.f,0.f,0.f);
    float4 a1 = a0, a2 = a0, a3 = a0;
#pragma unroll
    for (int i = 0; i < 16; i += 4) {
        float4 v0 = __ldcg(p + (i + 0) * 4 * F4);
        float4 v1 = __ldcg(p + (i + 1) * 4 * F4);
        float4 v2 = __ldcg(p + (i + 2) * 4 * F4);
        float4 v3 = __ldcg(p + (i + 3) * 4 * F4);
        a0.x += v0.x; a0.y += v0.y; a0.z += v0.z; a0.w += v0.w;
        a1.x += v1.x; a1.y += v1.y; a1.z += v1.z; a1.w += v1.w;
        a2.x += v2.x; a2.y += v2.y; a2.z += v2.z; a2.w += v2.w;
        a3.x += v3.x; a3.y += v3.y; a3.z += v3.z; a3.w += v3.w;
    }
    float4 acc;
    acc.x = (a0.x + a1.x) + (a2.x + a3.x);
    acc.y = (a0.y + a1.y) + (a2.y + a3.y);
    acc.z = (a0.z + a1.z) + (a2.z + a3.z);
    acc.w = (a0.w + a1.w) + (a2.w + a3.w);

    // ---- Phase 2: fold the 4 row-groups sharing a column (xor 8, 16).
#pragma unroll
    for (int m = 8; m <= 16; m <<= 1) {
        acc.x += __shfl_xor_sync(0xffffffffu, acc.x, m);
        acc.y += __shfl_xor_sync(0xffffffffu, acc.y, m);
        acc.z += __shfl_xor_sync(0xffffffffu, acc.z, m);
        acc.w += __shfl_xor_sync(0xffffffffu, acc.w, m);
    }
    if (lane < FSL4) part[w][lane] = acc;
    __syncthreads();

    // ---- Phase 3: fold 8 warp-partials (broadcast LDS, conflict-free).
    float4 s0 = part[0][c], s1 = part[1][c], s2 = part[2][c], s3 = part[3][c];
    {
        float4 w0 = part[4][c], w1 = part[5][c], w2 = part[6][c], w3 = part[7][c];
        s0.x += w0.x; s0.y += w0.y; s0.z += w0.z; s0.w += w0.w;
        s1.x += w1.x; s1.y += w1.y; s1.z += w1.z; s1.w += w1.w;
        s2.x += w2.x; s2.y += w2.y; s2.z += w2.z; s2.w += w2.w;
        s3.x += w3.x; s3.y += w3.y; s3.z += w3.z; s3.w += w3.w;
    }
    float4 t;
    t.x = (s0.x + s1.x) + (s2.x + s3.x);
    t.y = (s0.y + s1.y) + (s2.y + s3.y);
    t.z = (s0.z + s1.z) + (s2.z + s3.z);
    t.w = (s0.w + s1.w) + (s2.w + s3.w);

    // ---- Phase 4: two coalesced STG.128 per thread (rows r0 and r0+32).
    ob[0]       = t;
    ob[32 * F4] = t;
}

extern "C" void kernel_launch(void* const* d_in, const int* in_sizes, int n_in,
                              void* d_out, int out_size) {
    // inputs (metadata order): queries, keys, values, w_score
    const float4* values = (const float4*)d_in[2];
    float4* out = (float4*)d_out;
    feat_split_sum_broadcast<<<128, 256>>>(values, out);
}